// round 1
// baseline (speedup 1.0000x reference)
#include <cuda_runtime.h>
#include <math.h>

// Problem constants (fixed by the dataset: B=4, S=2048, H=1024, fp32)
#define SEQ 2048
#define HID 1024
#define NB  4
#define MT  (NB*SEQ)            // 8192 total rows

// ---------------------------------------------------------------------------
// Scratch (static device globals: allocation-free, graph-capture safe)
// ---------------------------------------------------------------------------
__device__ float g_xp [MT*HID];          // x + positional encoding
__device__ float g_q  [MT*HID];
__device__ float g_k  [MT*HID];
__device__ float g_v  [MT*HID];
__device__ float g_ctx[MT*HID];          // attn @ V
__device__ float g_o  [MT*HID];          // output projection (pre-LN)
__device__ float g_attn[(size_t)NB*SEQ*SEQ];   // scores -> softmax (in place)

// ---------------------------------------------------------------------------
// Kernel 1: xp = x + sinusoidal PE  (one thread per (sin,cos) pair)
// ---------------------------------------------------------------------------
__global__ void __launch_bounds__(256) add_pe_kernel(const float* __restrict__ x,
                                                     float* __restrict__ xp)
{
    int i   = blockIdx.x * blockDim.x + threadIdx.x;   // pair index, < MT*HID/2
    int h2  = i & (HID/2 - 1);                          // pair position 0..511
    int row = i >> 9;                                   // / (HID/2)
    int s   = row & (SEQ - 1);                          // sequence position
    // div = exp(2*h2 * (-ln(10000)/H))
    float div = expf((float)(2*h2) * (-9.210340371976184f / (float)HID));
    float sv, cv;
    sincosf((float)s * div, &sv, &cv);
    int base = 2*i;
    xp[base]   = x[base]   + sv;
    xp[base+1] = x[base+1] + cv;
}

// ---------------------------------------------------------------------------
// 128x128x8 SGEMM, 256 threads, 8x8 per-thread micro-tile.
//   TB=true : C[m,n] = sum_k A[m,k]*B[n,k]   (A:[M,K] rm, B:[N,K] rm)  "NT"
//   TB=false: C[m,n] = sum_k A[m,k]*B[k,n]   (B:[K,N] rm)              "NN"
// MODE 0: + bias[n]
// MODE 1: *scale + posb[m,n]; mask[m,n]==0 -> -1e9   (batched via blockIdx.z)
// MODE 2: plain
// Assumes M,N % 128 == 0 and K % 8 == 0 (true for all uses here).
// ---------------------------------------------------------------------------
template<int MODE, bool TB>
__global__ void __launch_bounds__(256, 2) gemm128(
    const float* __restrict__ A, const float* __restrict__ Bm, float* __restrict__ C,
    int M, int N, int K,
    int sA, int sB, int sC,
    const float* __restrict__ bias,
    const float* __restrict__ posb,
    const int*   __restrict__ mask, int sMask, float scale)
{
    const int bz = blockIdx.z;
    A  += (size_t)bz * sA;
    Bm += (size_t)bz * sB;
    C  += (size_t)bz * sC;

    __shared__ float As[8][128];
    __shared__ float Bs[8][128];

    const int tid = threadIdx.x;
    const int bm  = blockIdx.y * 128;
    const int bn  = blockIdx.x * 128;
    const int ty  = tid >> 4;          // 0..15 -> row group
    const int tx  = tid & 15;          // 0..15 -> col group

    // Staging indices: A-tile (and NT B-tile): 128 rows x 8 k, one float4/thread
    const int lrow = tid >> 1;
    const int lk   = (tid & 1) * 4;
    // NN B-tile: 8 k-rows x 128 n, one float4/thread
    const int bkr  = tid >> 5;
    const int bn4  = (tid & 31) * 4;

    float acc[8][8];
    #pragma unroll
    for (int i = 0; i < 8; i++)
        #pragma unroll
        for (int j = 0; j < 8; j++) acc[i][j] = 0.f;

    for (int k0 = 0; k0 < K; k0 += 8) {
        float4 av = *(const float4*)(A + (size_t)(bm + lrow) * K + k0 + lk);
        As[lk+0][lrow] = av.x; As[lk+1][lrow] = av.y;
        As[lk+2][lrow] = av.z; As[lk+3][lrow] = av.w;
        if (TB) {
            float4 bv = *(const float4*)(Bm + (size_t)(bn + lrow) * K + k0 + lk);
            Bs[lk+0][lrow] = bv.x; Bs[lk+1][lrow] = bv.y;
            Bs[lk+2][lrow] = bv.z; Bs[lk+3][lrow] = bv.w;
        } else {
            *(float4*)&Bs[bkr][bn4] =
                *(const float4*)(Bm + (size_t)(k0 + bkr) * N + bn + bn4);
        }
        __syncthreads();

        #pragma unroll
        for (int kk = 0; kk < 8; kk++) {
            float a[8], b[8];
            #pragma unroll
            for (int i = 0; i < 8; i++) a[i] = As[kk][ty*8 + i];
            #pragma unroll
            for (int j = 0; j < 8; j++) b[j] = Bs[kk][tx*8 + j];
            #pragma unroll
            for (int i = 0; i < 8; i++)
                #pragma unroll
                for (int j = 0; j < 8; j++)
                    acc[i][j] = fmaf(a[i], b[j], acc[i][j]);
        }
        __syncthreads();
    }

    if (MODE == 1) mask += (size_t)bz * sMask;

    #pragma unroll
    for (int i = 0; i < 8; i++) {
        const int row = bm + ty*8 + i;
        #pragma unroll
        for (int j = 0; j < 8; j++) {
            const int col = bn + tx*8 + j;
            float v = acc[i][j];
            if (MODE == 0) v += bias[col];
            if (MODE == 1) {
                v = v * scale + posb[(size_t)row * N + col];
                if (mask[(size_t)row * N + col] == 0) v = -1e9f;
            }
            C[(size_t)row * N + col] = v;
        }
    }
}

// ---------------------------------------------------------------------------
// Row softmax over [MT rows x SEQ cols], in place. 256 thr, 8 elems/thread.
// ---------------------------------------------------------------------------
__global__ void __launch_bounds__(256) softmax_kernel(float* __restrict__ attn)
{
    const size_t row = blockIdx.x;
    float* p = attn + row * SEQ;
    const int t    = threadIdx.x;
    const int w    = t >> 5;
    const int lane = t & 31;

    float4 u0 = *(float4*)(p + t*8);
    float4 u1 = *(float4*)(p + t*8 + 4);
    float v[8] = {u0.x, u0.y, u0.z, u0.w, u1.x, u1.y, u1.z, u1.w};

    float m = v[0];
    #pragma unroll
    for (int i = 1; i < 8; i++) m = fmaxf(m, v[i]);
    #pragma unroll
    for (int o = 16; o; o >>= 1) m = fmaxf(m, __shfl_xor_sync(0xffffffffu, m, o));

    __shared__ float smax[8];
    __shared__ float ssum[8];
    if (lane == 0) smax[w] = m;
    __syncthreads();
    float rm = smax[0];
    #pragma unroll
    for (int i = 1; i < 8; i++) rm = fmaxf(rm, smax[i]);

    float s = 0.f;
    #pragma unroll
    for (int i = 0; i < 8; i++) { v[i] = expf(v[i] - rm); s += v[i]; }
    #pragma unroll
    for (int o = 16; o; o >>= 1) s += __shfl_xor_sync(0xffffffffu, s, o);
    if (lane == 0) ssum[w] = s;
    __syncthreads();
    float tot = 0.f;
    #pragma unroll
    for (int i = 0; i < 8; i++) tot += ssum[i];
    const float inv = 1.f / tot;

    u0.x = v[0]*inv; u0.y = v[1]*inv; u0.z = v[2]*inv; u0.w = v[3]*inv;
    u1.x = v[4]*inv; u1.y = v[5]*inv; u1.z = v[6]*inv; u1.w = v[7]*inv;
    *(float4*)(p + t*8)     = u0;
    *(float4*)(p + t*8 + 4) = u1;
}

// ---------------------------------------------------------------------------
// LayerNorm(o + x) * gamma + beta.  256 thr, 4 elems/thread (HID=1024).
// ---------------------------------------------------------------------------
__global__ void __launch_bounds__(256) ln_kernel(
    const float* __restrict__ o, const float* __restrict__ x,
    const float* __restrict__ gamma, const float* __restrict__ beta,
    float* __restrict__ out)
{
    const size_t row = blockIdx.x;
    const float* po = o + row * HID;
    const float* px = x + row * HID;
    float* pout = out + row * HID;
    const int t    = threadIdx.x;
    const int w    = t >> 5;
    const int lane = t & 31;

    float4 a = *(const float4*)(po + t*4);
    float4 b = *(const float4*)(px + t*4);
    float h[4] = {a.x + b.x, a.y + b.y, a.z + b.z, a.w + b.w};

    float s  = h[0] + h[1] + h[2] + h[3];
    float sq = h[0]*h[0] + h[1]*h[1] + h[2]*h[2] + h[3]*h[3];
    #pragma unroll
    for (int off = 16; off; off >>= 1) {
        s  += __shfl_xor_sync(0xffffffffu, s,  off);
        sq += __shfl_xor_sync(0xffffffffu, sq, off);
    }
    __shared__ float rs[8], rq[8];
    if (lane == 0) { rs[w] = s; rq[w] = sq; }
    __syncthreads();
    float ts = 0.f, tq = 0.f;
    #pragma unroll
    for (int i = 0; i < 8; i++) { ts += rs[i]; tq += rq[i]; }

    const float mu  = ts * (1.f / HID);
    const float var = tq * (1.f / HID) - mu * mu;
    const float r   = rsqrtf(var + 1e-5f);

    float4 gv = *(const float4*)(gamma + t*4);
    float4 bv = *(const float4*)(beta  + t*4);
    float4 ov;
    ov.x = (h[0] - mu) * r * gv.x + bv.x;
    ov.y = (h[1] - mu) * r * gv.y + bv.y;
    ov.z = (h[2] - mu) * r * gv.z + bv.z;
    ov.w = (h[3] - mu) * r * gv.w + bv.w;
    *(float4*)(pout + t*4) = ov;
}

// ---------------------------------------------------------------------------
// Launch
// ---------------------------------------------------------------------------
extern "C" void kernel_launch(void* const* d_in, const int* in_sizes, int n_in,
                              void* d_out, int out_size)
{
    const float* x     = (const float*)d_in[0];
    const int*   mask  = (const int*)  d_in[1];
    const float* Wq    = (const float*)d_in[2];
    const float* bq    = (const float*)d_in[3];
    const float* Wk    = (const float*)d_in[4];
    const float* bk    = (const float*)d_in[5];
    const float* Wv    = (const float*)d_in[6];
    const float* bv    = (const float*)d_in[7];
    const float* posb  = (const float*)d_in[8];
    const float* Wo    = (const float*)d_in[9];
    const float* bo    = (const float*)d_in[10];
    const float* gamma = (const float*)d_in[11];
    const float* beta  = (const float*)d_in[12];
    float* out = (float*)d_out;

    float *xp, *q, *k, *v, *ctx, *o, *attn;
    cudaGetSymbolAddress((void**)&xp,   g_xp);
    cudaGetSymbolAddress((void**)&q,    g_q);
    cudaGetSymbolAddress((void**)&k,    g_k);
    cudaGetSymbolAddress((void**)&v,    g_v);
    cudaGetSymbolAddress((void**)&ctx,  g_ctx);
    cudaGetSymbolAddress((void**)&o,    g_o);
    cudaGetSymbolAddress((void**)&attn, g_attn);

    // 1) x + PE
    add_pe_kernel<<<(MT*HID/2)/256, 256>>>(x, xp);

    // 2) Q/K/V projections: [8192,1024] @ W^T + b   (NT)
    dim3 gp(HID/128, MT/128, 1);
    gemm128<0,true><<<gp, 256>>>(xp, Wq, q, MT, HID, HID, 0,0,0, bq, nullptr, nullptr, 0, 0.f);
    gemm128<0,true><<<gp, 256>>>(xp, Wk, k, MT, HID, HID, 0,0,0, bk, nullptr, nullptr, 0, 0.f);
    gemm128<0,true><<<gp, 256>>>(xp, Wv, v, MT, HID, HID, 0,0,0, bv, nullptr, nullptr, 0, 0.f);

    // 3) scores = Q K^T / 32 + pos_bias, masked   (batched NT)
    dim3 gs(SEQ/128, SEQ/128, NB);
    gemm128<1,true><<<gs, 256>>>(q, k, attn, SEQ, SEQ, HID,
                                 SEQ*HID, SEQ*HID, SEQ*SEQ,
                                 nullptr, posb, mask, SEQ*SEQ, 0.03125f);

    // 4) softmax (in place)
    softmax_kernel<<<MT, 256>>>(attn);

    // 5) context = attn @ V   (batched NN)
    dim3 gc(HID/128, SEQ/128, NB);
    gemm128<2,false><<<gc, 256>>>(attn, v, ctx, SEQ, HID, SEQ,
                                  SEQ*SEQ, SEQ*HID, SEQ*HID,
                                  nullptr, nullptr, nullptr, 0, 0.f);

    // 6) output projection
    gemm128<0,true><<<gp, 256>>>(ctx, Wo, o, MT, HID, HID, 0,0,0, bo, nullptr, nullptr, 0, 0.f);

    // 7) LayerNorm(out + x) -> first output
    ln_kernel<<<MT, 256>>>(o, x, gamma, beta, out);

    // 8) second output: attn probabilities
    if ((size_t)out_size >= (size_t)MT*HID + (size_t)NB*SEQ*SEQ) {
        cudaMemcpyAsync(out + (size_t)MT*HID, attn,
                        (size_t)NB*SEQ*SEQ*sizeof(float),
                        cudaMemcpyDeviceToDevice);
    }
}

// round 3
// speedup vs baseline: 2.3853x; 2.3853x over previous
#include <cuda_runtime.h>
#include <cuda_bf16.h>
#include <math.h>
#include <stdint.h>

#define SEQ 2048
#define HID 1024
#define NB  4
#define MT  (NB*SEQ)            // 8192

// ---------------------------------------------------------------------------
// Scratch (device globals — allocation-free)
// ---------------------------------------------------------------------------
__device__ __align__(256) __nv_bfloat16 g_xp_h[MT*HID],  g_xp_l[MT*HID];
__device__ __align__(256) __nv_bfloat16 g_q_h [MT*HID],  g_q_l [MT*HID];
__device__ __align__(256) __nv_bfloat16 g_k_h [MT*HID],  g_k_l [MT*HID];
__device__ __align__(256) __nv_bfloat16 g_vt_h[(size_t)HID*MT], g_vt_l[(size_t)HID*MT]; // V^T
__device__ __align__(256) __nv_bfloat16 g_cx_h[MT*HID],  g_cx_l[MT*HID];
__device__ __align__(256) __nv_bfloat16 g_wq_h[HID*HID], g_wq_l[HID*HID];
__device__ __align__(256) __nv_bfloat16 g_wk_h[HID*HID], g_wk_l[HID*HID];
__device__ __align__(256) __nv_bfloat16 g_wv_h[HID*HID], g_wv_l[HID*HID];
__device__ __align__(256) __nv_bfloat16 g_wo_h[HID*HID], g_wo_l[HID*HID];
__device__ __align__(256) __nv_bfloat16 g_at_h[(size_t)NB*SEQ*SEQ], g_at_l[(size_t)NB*SEQ*SEQ];
__device__ __align__(256) float g_scores[(size_t)NB*SEQ*SEQ];
__device__ __align__(256) float g_o[MT*HID];

// ---------------------------------------------------------------------------
// Helpers
// ---------------------------------------------------------------------------
__device__ __forceinline__ uint32_t smem_u32(const void* p) {
    uint32_t a;
    asm("{ .reg .u64 t; cvta.to.shared.u64 t, %1; cvt.u32.u64 %0, t; }" : "=r"(a) : "l"(p));
    return a;
}
__device__ __forceinline__ void cp16(uint32_t s, const void* g) {
    asm volatile("cp.async.cg.shared.global [%0], [%1], 16;" :: "r"(s), "l"(g));
}
#define CP_COMMIT() asm volatile("cp.async.commit_group;" ::: "memory")

__device__ __forceinline__ void ldsm_x4(uint32_t& r0, uint32_t& r1, uint32_t& r2, uint32_t& r3, uint32_t a) {
    asm volatile("ldmatrix.sync.aligned.m8n8.x4.shared.b16 {%0,%1,%2,%3}, [%4];"
                 : "=r"(r0), "=r"(r1), "=r"(r2), "=r"(r3) : "r"(a));
}
__device__ __forceinline__ void mma_bf16(float* c, const uint32_t* a, const uint32_t* b) {
    asm volatile("mma.sync.aligned.m16n8k16.row.col.f32.bf16.bf16.f32 "
                 "{%0,%1,%2,%3}, {%4,%5,%6,%7}, {%8,%9}, {%0,%1,%2,%3};"
                 : "+f"(c[0]), "+f"(c[1]), "+f"(c[2]), "+f"(c[3])
                 : "r"(a[0]), "r"(a[1]), "r"(a[2]), "r"(a[3]), "r"(b[0]), "r"(b[1]));
}

__device__ __forceinline__ void split1(float v, uint16_t& h, uint16_t& l) {
    __nv_bfloat16 bh = __float2bfloat16(v);
    float fh = __bfloat162float(bh);
    __nv_bfloat16 bl = __float2bfloat16(v - fh);
    h = __bfloat16_as_ushort(bh);
    l = __bfloat16_as_ushort(bl);
}
__device__ __forceinline__ void split_pack(float v0, float v1, uint32_t& hp, uint32_t& lp) {
    uint16_t h0, l0, h1, l1;
    split1(v0, h0, l0); split1(v1, h1, l1);
    hp = (uint32_t)h0 | ((uint32_t)h1 << 16);
    lp = (uint32_t)l0 | ((uint32_t)l1 << 16);
}

// ---------------------------------------------------------------------------
// bf16x2-split NT GEMM via mma.sync:  D(128x128) = A(128xK) * B(128xK)^T
//   C = Ah*Bh + Ah*Bl + Al*Bh   (fp32 accum)
// MODE 0: bf16-split out (+optional bias)
// MODE 1: bf16-split out TRANSPOSED (+bias)   (for V^T)
// MODE 2: fp32 scores: *scale + posb, mask==0 -> -1e9
// MODE 3: fp32 + bias
// ---------------------------------------------------------------------------
#define LDT 40                         // halves per smem row (32 + 8 skew)
#define TILE_B (128*LDT*2)             // 10240 B
#define STAGE_B (4*TILE_B)             // 40960 B  (Ah, Al, Bh, Bl)
#define NSTAGE 3
#define SMEM_BYTES (NSTAGE*STAGE_B)    // 122880 B

__device__ __forceinline__ void load_stage(
    uint32_t sb,
    const __nv_bfloat16* __restrict__ Ah, const __nv_bfloat16* __restrict__ Al,
    const __nv_bfloat16* __restrict__ Bh, const __nv_bfloat16* __restrict__ Bl,
    int lda, int ldb, int bm, int bn, int k0, int tid)
{
    const int row = tid >> 2;          // 0..63
    const int kc  = (tid & 3) * 8;     // half offset within 32
    #pragma unroll
    for (int h = 0; h < 2; h++) {
        const int r = row + h * 64;
        const uint32_t so = (uint32_t)(r * LDT + kc) * 2;
        cp16(sb + 0*TILE_B + so, Ah + (size_t)(bm + r) * lda + k0 + kc);
        cp16(sb + 1*TILE_B + so, Al + (size_t)(bm + r) * lda + k0 + kc);
        cp16(sb + 2*TILE_B + so, Bh + (size_t)(bn + r) * ldb + k0 + kc);
        cp16(sb + 3*TILE_B + so, Bl + (size_t)(bn + r) * ldb + k0 + kc);
    }
    CP_COMMIT();
}

template<int MODE>
__global__ void __launch_bounds__(256, 1) tc_gemm(
    const __nv_bfloat16* __restrict__ Ah, const __nv_bfloat16* __restrict__ Al,
    const __nv_bfloat16* __restrict__ Bh, const __nv_bfloat16* __restrict__ Bl,
    int K, int lda, int ldb,
    long long sA, long long sB, long long sC,
    float* __restrict__ Cf,
    __nv_bfloat16* __restrict__ Chi, __nv_bfloat16* __restrict__ Clo,
    int ldc, int ldct,
    const float* __restrict__ bias,
    const float* __restrict__ posb, const int* __restrict__ maskp, float scale)
{
    extern __shared__ char smem[];
    const uint32_t sbase = smem_u32(smem);

    const int tid  = threadIdx.x;
    const int wid  = tid >> 5;
    const int lane = tid & 31;
    const int bm = blockIdx.y * 128, bn = blockIdx.x * 128, bz = blockIdx.z;
    const int m0 = (wid & 1) * 64;     // warp M offset within CTA tile
    const int n0 = (wid >> 1) * 32;    // warp N offset

    Ah += (size_t)bz * sA;  Al += (size_t)bz * sA;
    Bh += (size_t)bz * sB;  Bl += (size_t)bz * sB;

    float acc[4][4][4];
    #pragma unroll
    for (int i = 0; i < 4; i++)
        #pragma unroll
        for (int j = 0; j < 4; j++)
            #pragma unroll
            for (int e = 0; e < 4; e++) acc[i][j][e] = 0.f;

    const int NC = K >> 5;             // 32-wide k chunks

    load_stage(sbase,           Ah, Al, Bh, Bl, lda, ldb, bm, bn, 0,  tid);
    load_stage(sbase + STAGE_B, Ah, Al, Bh, Bl, lda, ldb, bm, bn, 32, tid);

    // ldmatrix lane-address components
    const int arow  = lane & 15;
    const int akoff = (lane >> 4) * 8;
    const int noff  = (lane & 7) + ((lane >> 4) << 3);
    const int bkoff = ((lane >> 3) & 1) * 8;

    for (int c = 0; c < NC; c++) {
        if (c == NC - 1) asm volatile("cp.async.wait_group 0;" ::: "memory");
        else             asm volatile("cp.async.wait_group 1;" ::: "memory");
        __syncthreads();
        if (c + 2 < NC)
            load_stage(sbase + ((c + 2) % NSTAGE) * STAGE_B,
                       Ah, Al, Bh, Bl, lda, ldb, bm, bn, (c + 2) * 32, tid);

        const uint32_t st = sbase + (c % NSTAGE) * STAGE_B;
        const uint32_t sAh = st, sAl = st + TILE_B, sBh = st + 2*TILE_B, sBl = st + 3*TILE_B;

        #pragma unroll
        for (int k16 = 0; k16 < 32; k16 += 16) {
            uint32_t aH[4][4], aL[4][4], bH[2][4], bL[2][4];
            #pragma unroll
            for (int mi = 0; mi < 4; mi++) {
                const uint32_t ao = (uint32_t)((m0 + mi*16 + arow) * LDT + k16 + akoff) * 2;
                ldsm_x4(aH[mi][0], aH[mi][1], aH[mi][2], aH[mi][3], sAh + ao);
                ldsm_x4(aL[mi][0], aL[mi][1], aL[mi][2], aL[mi][3], sAl + ao);
            }
            #pragma unroll
            for (int nb = 0; nb < 2; nb++) {
                const uint32_t bo = (uint32_t)((n0 + nb*16 + noff) * LDT + k16 + bkoff) * 2;
                ldsm_x4(bH[nb][0], bH[nb][1], bH[nb][2], bH[nb][3], sBh + bo);
                ldsm_x4(bL[nb][0], bL[nb][1], bL[nb][2], bL[nb][3], sBl + bo);
            }
            #pragma unroll
            for (int mi = 0; mi < 4; mi++)
                #pragma unroll
                for (int ni = 0; ni < 4; ni++) {
                    const uint32_t* bh = &bH[ni >> 1][(ni & 1) * 2];
                    const uint32_t* bl = &bL[ni >> 1][(ni & 1) * 2];
                    mma_bf16(acc[mi][ni], aH[mi], bh);
                    mma_bf16(acc[mi][ni], aH[mi], bl);
                    mma_bf16(acc[mi][ni], aL[mi], bh);
                }
        }
        __syncthreads();
    }

    // ------------------------------ epilogue ------------------------------
    if (MODE == 1) {
        // transpose through smem: T[128][132] fp32 (66 KB, fits in pipeline smem)
        float* T = (float*)smem;
        #pragma unroll
        for (int mi = 0; mi < 4; mi++)
            #pragma unroll
            for (int ni = 0; ni < 4; ni++) {
                const int ml = m0 + mi*16 + (lane >> 2);
                const int nl = n0 + ni*8 + (lane & 3) * 2;
                const float b0 = bias[bn + nl], b1 = bias[bn + nl + 1];
                T[ml * 132 + nl]           = acc[mi][ni][0] + b0;
                T[ml * 132 + nl + 1]       = acc[mi][ni][1] + b1;
                T[(ml + 8) * 132 + nl]     = acc[mi][ni][2] + b0;
                T[(ml + 8) * 132 + nl + 1] = acc[mi][ni][3] + b1;
            }
        __syncthreads();
        const int n  = tid >> 1;              // 0..127 column of tile
        const int mh = (tid & 1) * 64;        // half of M range
        uint32_t* ph = (uint32_t*)(Chi + (size_t)(bn + n) * ldct + bm + mh);
        uint32_t* pl = (uint32_t*)(Clo + (size_t)(bn + n) * ldct + bm + mh);
        #pragma unroll
        for (int m = 0; m < 64; m += 2) {
            uint32_t hp, lp;
            split_pack(T[(mh + m) * 132 + n], T[(mh + m + 1) * 132 + n], hp, lp);
            ph[m >> 1] = hp;  pl[m >> 1] = lp;
        }
    } else {
        #pragma unroll
        for (int mi = 0; mi < 4; mi++)
            #pragma unroll
            for (int ni = 0; ni < 4; ni++) {
                const int rb = bm + m0 + mi*16 + (lane >> 2);
                const int cb = bn + n0 + ni*8 + (lane & 3) * 2;
                #pragma unroll
                for (int half = 0; half < 2; half++) {
                    const int r = rb + half * 8;
                    const float v0 = acc[mi][ni][half*2];
                    const float v1 = acc[mi][ni][half*2 + 1];
                    if (MODE == 0) {
                        __nv_bfloat16* Ch = Chi + (size_t)bz * sC;
                        __nv_bfloat16* Cl = Clo + (size_t)bz * sC;
                        float w0 = v0, w1 = v1;
                        if (bias) { w0 += bias[cb]; w1 += bias[cb + 1]; }
                        uint32_t hp, lp;
                        split_pack(w0, w1, hp, lp);
                        *(uint32_t*)(Ch + (size_t)r * ldc + cb) = hp;
                        *(uint32_t*)(Cl + (size_t)r * ldc + cb) = lp;
                    } else if (MODE == 2) {
                        float* C = Cf + (size_t)bz * sC;
                        const int* mk = maskp + (size_t)bz * sC;
                        const size_t off = (size_t)r * ldc + cb;
                        const float2 pb = *(const float2*)(posb + off);
                        const int2   mm = *(const int2*)(mk + off);
                        float2 o;
                        o.x = mm.x ? fmaf(v0, scale, pb.x) : -1e9f;
                        o.y = mm.y ? fmaf(v1, scale, pb.y) : -1e9f;
                        *(float2*)(C + off) = o;
                    } else {  // MODE 3
                        float2 o;
                        o.x = v0 + bias[cb];
                        o.y = v1 + bias[cb + 1];
                        *(float2*)(Cf + (size_t)r * ldc + cb) = o;
                    }
                }
            }
    }
}

// ---------------------------------------------------------------------------
// xp = x + PE, bf16-split
// ---------------------------------------------------------------------------
__global__ void __launch_bounds__(256) pe_split_kernel(
    const float* __restrict__ x, __nv_bfloat16* __restrict__ xh, __nv_bfloat16* __restrict__ xl)
{
    int i   = blockIdx.x * blockDim.x + threadIdx.x;
    int h2  = i & (HID / 2 - 1);
    int row = i >> 9;
    int s   = row & (SEQ - 1);
    float div = expf((float)(2 * h2) * (-9.210340371976184f / (float)HID));
    float sv, cv;
    sincosf((float)s * div, &sv, &cv);
    int base = 2 * i;
    uint32_t hp, lp;
    split_pack(x[base] + sv, x[base + 1] + cv, hp, lp);
    ((uint32_t*)xh)[i] = hp;
    ((uint32_t*)xl)[i] = lp;
}

__global__ void __launch_bounds__(256) wsplit_kernel(
    const float* __restrict__ w, __nv_bfloat16* __restrict__ wh, __nv_bfloat16* __restrict__ wl)
{
    int i4 = (blockIdx.x * blockDim.x + threadIdx.x) * 4;
    float4 v = *(const float4*)(w + i4);
    uint32_t h0, l0, h1, l1;
    split_pack(v.x, v.y, h0, l0);
    split_pack(v.z, v.w, h1, l1);
    ((uint2*)wh)[i4 >> 2] = make_uint2(h0, h1);
    ((uint2*)wl)[i4 >> 2] = make_uint2(l0, l1);
}

// ---------------------------------------------------------------------------
// softmax; writes fp32 probs to out2 and bf16 split for the attn@V GEMM
// ---------------------------------------------------------------------------
__global__ void __launch_bounds__(256) softmax_split_kernel(
    const float* __restrict__ scores, float* __restrict__ out2,
    __nv_bfloat16* __restrict__ ah, __nv_bfloat16* __restrict__ al)
{
    const size_t row = blockIdx.x;
    const float* p = scores + row * SEQ;
    const int t = threadIdx.x, w = t >> 5, lane = t & 31;

    float4 u0 = *(const float4*)(p + t * 8);
    float4 u1 = *(const float4*)(p + t * 8 + 4);
    float v[8] = {u0.x, u0.y, u0.z, u0.w, u1.x, u1.y, u1.z, u1.w};

    float m = v[0];
    #pragma unroll
    for (int i = 1; i < 8; i++) m = fmaxf(m, v[i]);
    #pragma unroll
    for (int o = 16; o; o >>= 1) m = fmaxf(m, __shfl_xor_sync(0xffffffffu, m, o));
    __shared__ float smax[8], ssum[8];
    if (lane == 0) smax[w] = m;
    __syncthreads();
    float rm = smax[0];
    #pragma unroll
    for (int i = 1; i < 8; i++) rm = fmaxf(rm, smax[i]);

    float s = 0.f;
    #pragma unroll
    for (int i = 0; i < 8; i++) { v[i] = expf(v[i] - rm); s += v[i]; }
    #pragma unroll
    for (int o = 16; o; o >>= 1) s += __shfl_xor_sync(0xffffffffu, s, o);
    if (lane == 0) ssum[w] = s;
    __syncthreads();
    float tot = 0.f;
    #pragma unroll
    for (int i = 0; i < 8; i++) tot += ssum[i];
    const float inv = 1.f / tot;
    #pragma unroll
    for (int i = 0; i < 8; i++) v[i] *= inv;

    float* po = out2 + row * SEQ + t * 8;
    *(float4*)(po)     = make_float4(v[0], v[1], v[2], v[3]);
    *(float4*)(po + 4) = make_float4(v[4], v[5], v[6], v[7]);

    uint32_t* ph = (uint32_t*)(ah + row * SEQ) + t * 4;
    uint32_t* pl = (uint32_t*)(al + row * SEQ) + t * 4;
    #pragma unroll
    for (int i = 0; i < 4; i++) {
        uint32_t hp, lp;
        split_pack(v[2 * i], v[2 * i + 1], hp, lp);
        ph[i] = hp;  pl[i] = lp;
    }
}

// ---------------------------------------------------------------------------
// LayerNorm(o + x)
// ---------------------------------------------------------------------------
__global__ void __launch_bounds__(256) ln_kernel(
    const float* __restrict__ o, const float* __restrict__ x,
    const float* __restrict__ gamma, const float* __restrict__ beta,
    float* __restrict__ out)
{
    const size_t row = blockIdx.x;
    const float* po = o + row * HID;
    const float* px = x + row * HID;
    float* pout = out + row * HID;
    const int t = threadIdx.x, w = t >> 5, lane = t & 31;

    float4 a = *(const float4*)(po + t * 4);
    float4 b = *(const float4*)(px + t * 4);
    float h[4] = {a.x + b.x, a.y + b.y, a.z + b.z, a.w + b.w};

    float s  = h[0] + h[1] + h[2] + h[3];
    float sq = h[0]*h[0] + h[1]*h[1] + h[2]*h[2] + h[3]*h[3];
    #pragma unroll
    for (int off = 16; off; off >>= 1) {
        s  += __shfl_xor_sync(0xffffffffu, s,  off);
        sq += __shfl_xor_sync(0xffffffffu, sq, off);
    }
    __shared__ float rs[8], rq[8];
    if (lane == 0) { rs[w] = s; rq[w] = sq; }
    __syncthreads();
    float ts = 0.f, tq = 0.f;
    #pragma unroll
    for (int i = 0; i < 8; i++) { ts += rs[i]; tq += rq[i]; }

    const float mu  = ts * (1.f / HID);
    const float var = tq * (1.f / HID) - mu * mu;
    const float r   = rsqrtf(var + 1e-5f);

    float4 gv = *(const float4*)(gamma + t * 4);
    float4 bv = *(const float4*)(beta  + t * 4);
    float4 ov;
    ov.x = (h[0] - mu) * r * gv.x + bv.x;
    ov.y = (h[1] - mu) * r * gv.y + bv.y;
    ov.z = (h[2] - mu) * r * gv.z + bv.z;
    ov.w = (h[3] - mu) * r * gv.w + bv.w;
    *(float4*)(pout + t * 4) = ov;
}

// ---------------------------------------------------------------------------
// Launch
// ---------------------------------------------------------------------------
extern "C" void kernel_launch(void* const* d_in, const int* in_sizes, int n_in,
                              void* d_out, int out_size)
{
    const float* x     = (const float*)d_in[0];
    const int*   mask  = (const int*)  d_in[1];
    const float* Wq    = (const float*)d_in[2];
    const float* bq    = (const float*)d_in[3];
    const float* Wk    = (const float*)d_in[4];
    const float* bk    = (const float*)d_in[5];
    const float* Wv    = (const float*)d_in[6];
    const float* bv    = (const float*)d_in[7];
    const float* posb  = (const float*)d_in[8];
    const float* Wo    = (const float*)d_in[9];
    const float* bo    = (const float*)d_in[10];
    const float* gamma = (const float*)d_in[11];
    const float* beta  = (const float*)d_in[12];
    float* out  = (float*)d_out;
    float* out2 = out + (size_t)MT * HID;

    __nv_bfloat16 *xph, *xpl, *qh, *ql, *kh, *kl, *vth, *vtl, *cxh, *cxl;
    __nv_bfloat16 *wqh, *wql, *wkh, *wkl, *wvh, *wvl, *woh, *wol, *ath, *atl;
    float *scores, *o;
    cudaGetSymbolAddress((void**)&xph, g_xp_h);  cudaGetSymbolAddress((void**)&xpl, g_xp_l);
    cudaGetSymbolAddress((void**)&qh,  g_q_h);   cudaGetSymbolAddress((void**)&ql,  g_q_l);
    cudaGetSymbolAddress((void**)&kh,  g_k_h);   cudaGetSymbolAddress((void**)&kl,  g_k_l);
    cudaGetSymbolAddress((void**)&vth, g_vt_h);  cudaGetSymbolAddress((void**)&vtl, g_vt_l);
    cudaGetSymbolAddress((void**)&cxh, g_cx_h);  cudaGetSymbolAddress((void**)&cxl, g_cx_l);
    cudaGetSymbolAddress((void**)&wqh, g_wq_h);  cudaGetSymbolAddress((void**)&wql, g_wq_l);
    cudaGetSymbolAddress((void**)&wkh, g_wk_h);  cudaGetSymbolAddress((void**)&wkl, g_wk_l);
    cudaGetSymbolAddress((void**)&wvh, g_wv_h);  cudaGetSymbolAddress((void**)&wvl, g_wv_l);
    cudaGetSymbolAddress((void**)&woh, g_wo_h);  cudaGetSymbolAddress((void**)&wol, g_wo_l);
    cudaGetSymbolAddress((void**)&ath, g_at_h);  cudaGetSymbolAddress((void**)&atl, g_at_l);
    cudaGetSymbolAddress((void**)&scores, g_scores);
    cudaGetSymbolAddress((void**)&o, g_o);

    cudaFuncSetAttribute(tc_gemm<0>, cudaFuncAttributeMaxDynamicSharedMemorySize, SMEM_BYTES);
    cudaFuncSetAttribute(tc_gemm<1>, cudaFuncAttributeMaxDynamicSharedMemorySize, SMEM_BYTES);
    cudaFuncSetAttribute(tc_gemm<2>, cudaFuncAttributeMaxDynamicSharedMemorySize, SMEM_BYTES);
    cudaFuncSetAttribute(tc_gemm<3>, cudaFuncAttributeMaxDynamicSharedMemorySize, SMEM_BYTES);

    // 1) xp = x + PE, split
    pe_split_kernel<<<(MT * HID / 2) / 256, 256>>>(x, xph, xpl);

    // 2) weight splits
    const int wg = (HID * HID / 4) / 256;
    wsplit_kernel<<<wg, 256>>>(Wq, wqh, wql);
    wsplit_kernel<<<wg, 256>>>(Wk, wkh, wkl);
    wsplit_kernel<<<wg, 256>>>(Wv, wvh, wvl);
    wsplit_kernel<<<wg, 256>>>(Wo, woh, wol);

    // 3) Q/K/V projections  [8192,1024] @ W^T + b
    dim3 gp(HID / 128, MT / 128, 1);
    tc_gemm<0><<<gp, 256, SMEM_BYTES>>>(xph, xpl, wqh, wql, HID, HID, HID, 0, 0, 0,
        nullptr, qh, ql, HID, 0, bq, nullptr, nullptr, 0.f);
    tc_gemm<0><<<gp, 256, SMEM_BYTES>>>(xph, xpl, wkh, wkl, HID, HID, HID, 0, 0, 0,
        nullptr, kh, kl, HID, 0, bk, nullptr, nullptr, 0.f);
    tc_gemm<1><<<gp, 256, SMEM_BYTES>>>(xph, xpl, wvh, wvl, HID, HID, HID, 0, 0, 0,
        nullptr, vth, vtl, 0, MT, bv, nullptr, nullptr, 0.f);

    // 4) scores = QK^T/32 + pos_bias, masked
    dim3 gs(SEQ / 128, SEQ / 128, NB);
    tc_gemm<2><<<gs, 256, SMEM_BYTES>>>(qh, ql, kh, kl, HID, HID, HID,
        (long long)SEQ * HID, (long long)SEQ * HID, (long long)SEQ * SEQ,
        scores, nullptr, nullptr, SEQ, 0, nullptr, posb, mask, 0.03125f);

    // 5) softmax + split (+ attn probs output)
    softmax_split_kernel<<<MT, 256>>>(scores, out2, ath, atl);

    // 6) context = attn @ V   (B = V^T, NT)
    dim3 gc(HID / 128, SEQ / 128, NB);
    tc_gemm<0><<<gc, 256, SMEM_BYTES>>>(ath, atl, vth, vtl, SEQ, SEQ, MT,
        (long long)SEQ * SEQ, (long long)SEQ, (long long)SEQ * HID,
        nullptr, cxh, cxl, HID, 0, nullptr, nullptr, nullptr, 0.f);

    // 7) output projection -> o (fp32)
    tc_gemm<3><<<gp, 256, SMEM_BYTES>>>(cxh, cxl, woh, wol, HID, HID, HID, 0, 0, 0,
        o, nullptr, nullptr, HID, 0, bo, nullptr, nullptr, 0.f);

    // 8) LayerNorm(o + x)
    ln_kernel<<<MT, 256>>>(o, x, gamma, beta, out);
}

// round 4
// speedup vs baseline: 2.7802x; 1.1656x over previous
#include <cuda_runtime.h>
#include <cuda_bf16.h>
#include <math.h>
#include <stdint.h>

#define SEQ 2048
#define HID 1024
#define NB  4
#define MT  (NB*SEQ)            // 8192

// ---------------------------------------------------------------------------
// Scratch (device globals — allocation-free)
// ---------------------------------------------------------------------------
__device__ __align__(256) __nv_bfloat16 g_xp_h[MT*HID],  g_xp_l[MT*HID];
__device__ __align__(256) __nv_bfloat16 g_q_h [MT*HID],  g_q_l [MT*HID];
__device__ __align__(256) __nv_bfloat16 g_k_h [MT*HID],  g_k_l [MT*HID];
__device__ __align__(256) __nv_bfloat16 g_vt_h[(size_t)HID*MT], g_vt_l[(size_t)HID*MT]; // V^T
__device__ __align__(256) __nv_bfloat16 g_cx_h[MT*HID],  g_cx_l[MT*HID];
__device__ __align__(256) __nv_bfloat16 g_wq_h[HID*HID], g_wq_l[HID*HID];
__device__ __align__(256) __nv_bfloat16 g_wk_h[HID*HID], g_wk_l[HID*HID];
__device__ __align__(256) __nv_bfloat16 g_wv_h[HID*HID], g_wv_l[HID*HID];
__device__ __align__(256) __nv_bfloat16 g_wo_h[HID*HID], g_wo_l[HID*HID];
__device__ __align__(256) __nv_bfloat16 g_at_h[(size_t)NB*SEQ*SEQ], g_at_l[(size_t)NB*SEQ*SEQ];
__device__ __align__(256) float g_scores[(size_t)NB*SEQ*SEQ];
__device__ __align__(256) float g_o[MT*HID];

// ---------------------------------------------------------------------------
// Helpers
// ---------------------------------------------------------------------------
__device__ __forceinline__ uint32_t smem_u32(const void* p) {
    uint32_t a;
    asm("{ .reg .u64 t; cvta.to.shared.u64 t, %1; cvt.u32.u64 %0, t; }" : "=r"(a) : "l"(p));
    return a;
}
__device__ __forceinline__ void cp16(uint32_t s, const void* g) {
    asm volatile("cp.async.cg.shared.global [%0], [%1], 16;" :: "r"(s), "l"(g));
}
#define CP_COMMIT() asm volatile("cp.async.commit_group;" ::: "memory")

__device__ __forceinline__ void ldsm_x4(uint32_t& r0, uint32_t& r1, uint32_t& r2, uint32_t& r3, uint32_t a) {
    asm volatile("ldmatrix.sync.aligned.m8n8.x4.shared.b16 {%0,%1,%2,%3}, [%4];"
                 : "=r"(r0), "=r"(r1), "=r"(r2), "=r"(r3) : "r"(a));
}
__device__ __forceinline__ void mma_bf16(float* c, const uint32_t* a, const uint32_t* b) {
    asm volatile("mma.sync.aligned.m16n8k16.row.col.f32.bf16.bf16.f32 "
                 "{%0,%1,%2,%3}, {%4,%5,%6,%7}, {%8,%9}, {%0,%1,%2,%3};"
                 : "+f"(c[0]), "+f"(c[1]), "+f"(c[2]), "+f"(c[3])
                 : "r"(a[0]), "r"(a[1]), "r"(a[2]), "r"(a[3]), "r"(b[0]), "r"(b[1]));
}

__device__ __forceinline__ void split1(float v, uint16_t& h, uint16_t& l) {
    __nv_bfloat16 bh = __float2bfloat16(v);
    float fh = __bfloat162float(bh);
    __nv_bfloat16 bl = __float2bfloat16(v - fh);
    h = __bfloat16_as_ushort(bh);
    l = __bfloat16_as_ushort(bl);
}
__device__ __forceinline__ void split_pack(float v0, float v1, uint32_t& hp, uint32_t& lp) {
    uint16_t h0, l0, h1, l1;
    split1(v0, h0, l0); split1(v1, h1, l1);
    hp = (uint32_t)h0 | ((uint32_t)h1 << 16);
    lp = (uint32_t)l0 | ((uint32_t)l1 << 16);
}

// ---------------------------------------------------------------------------
// bf16x2-split NT GEMM via mma.sync:  D(128x128) = A(128xK) * B(128xK)^T
//   C = Ah*Bh + Ah*Bl + Al*Bh   (fp32 accum)
// 128 threads, 4 warps (2x2), 64x64 warp tiles, 2-stage cp.async, 2 CTAs/SM.
// MODE 0: bf16-split out (+optional bias)
// MODE 1: bf16-split out TRANSPOSED (+bias)   (for V^T)
// MODE 2: fp32 scores: *scale + posb, mask==0 -> -1e9
// MODE 3: fp32 + bias
// ---------------------------------------------------------------------------
#define LDT 40                         // halves per smem row (32 + 8 skew)
#define TILE_B (128*LDT*2)             // 10240 B
#define STAGE_B (4*TILE_B)             // 40960 B  (Ah, Al, Bh, Bl)
#define SMEM_BYTES (2*STAGE_B)         // 81920 B

__device__ __forceinline__ void load_stage(
    uint32_t sb,
    const __nv_bfloat16* __restrict__ Ah, const __nv_bfloat16* __restrict__ Al,
    const __nv_bfloat16* __restrict__ Bh, const __nv_bfloat16* __restrict__ Bl,
    int lda, int ldb, int bm, int bn, int k0, int tid)
{
    const int row = tid >> 2;          // 0..31
    const int kc  = (tid & 3) * 8;     // half offset within 32
    #pragma unroll
    for (int h = 0; h < 4; h++) {
        const int r = row + h * 32;
        const uint32_t so = (uint32_t)(r * LDT + kc) * 2;
        cp16(sb + 0*TILE_B + so, Ah + (size_t)(bm + r) * lda + k0 + kc);
        cp16(sb + 1*TILE_B + so, Al + (size_t)(bm + r) * lda + k0 + kc);
        cp16(sb + 2*TILE_B + so, Bh + (size_t)(bn + r) * ldb + k0 + kc);
        cp16(sb + 3*TILE_B + so, Bl + (size_t)(bn + r) * ldb + k0 + kc);
    }
    CP_COMMIT();
}

template<int MODE>
__global__ void __launch_bounds__(128, 2) tc_gemm(
    const __nv_bfloat16* __restrict__ Ah, const __nv_bfloat16* __restrict__ Al,
    const __nv_bfloat16* __restrict__ Bh, const __nv_bfloat16* __restrict__ Bl,
    int K, int lda, int ldb,
    long long sA, long long sB, long long sC,
    float* __restrict__ Cf,
    __nv_bfloat16* __restrict__ Chi, __nv_bfloat16* __restrict__ Clo,
    int ldc, int ldct,
    const float* __restrict__ bias,
    const float* __restrict__ posb, const int* __restrict__ maskp, float scale)
{
    extern __shared__ char smem[];
    const uint32_t sbase = smem_u32(smem);

    const int tid  = threadIdx.x;
    const int wid  = tid >> 5;
    const int lane = tid & 31;
    const int bm = blockIdx.y * 128, bn = blockIdx.x * 128, bz = blockIdx.z;
    const int m0 = (wid & 1) * 64;     // warp M offset
    const int n0 = (wid >> 1) * 64;    // warp N offset

    Ah += (size_t)bz * sA;  Al += (size_t)bz * sA;
    Bh += (size_t)bz * sB;  Bl += (size_t)bz * sB;

    float acc[4][8][4];
    #pragma unroll
    for (int i = 0; i < 4; i++)
        #pragma unroll
        for (int j = 0; j < 8; j++)
            #pragma unroll
            for (int e = 0; e < 4; e++) acc[i][j][e] = 0.f;

    const int NC = K >> 5;             // 32-wide k chunks

    load_stage(sbase, Ah, Al, Bh, Bl, lda, ldb, bm, bn, 0, tid);

    // ldmatrix lane-address components
    const int arow  = lane & 15;
    const int akoff = (lane >> 4) * 8;
    const int noff  = (lane & 7) + ((lane >> 4) << 3);
    const int bkoff = ((lane >> 3) & 1) * 8;

    for (int c = 0; c < NC; c++) {
        asm volatile("cp.async.wait_group 0;" ::: "memory");
        __syncthreads();
        if (c + 1 < NC)
            load_stage(sbase + ((c + 1) & 1) * STAGE_B,
                       Ah, Al, Bh, Bl, lda, ldb, bm, bn, (c + 1) * 32, tid);

        const uint32_t st = sbase + (c & 1) * STAGE_B;
        const uint32_t sAh = st, sAl = st + TILE_B, sBh = st + 2*TILE_B, sBl = st + 3*TILE_B;

        #pragma unroll
        for (int k16 = 0; k16 < 32; k16 += 16) {
            uint32_t aH[4][4], aL[4][4];
            #pragma unroll
            for (int mi = 0; mi < 4; mi++) {
                const uint32_t ao = (uint32_t)((m0 + mi*16 + arow) * LDT + k16 + akoff) * 2;
                ldsm_x4(aH[mi][0], aH[mi][1], aH[mi][2], aH[mi][3], sAh + ao);
                ldsm_x4(aL[mi][0], aL[mi][1], aL[mi][2], aL[mi][3], sAl + ao);
            }
            #pragma unroll
            for (int half = 0; half < 2; half++) {
                uint32_t bH[2][4], bL[2][4];
                #pragma unroll
                for (int nb = 0; nb < 2; nb++) {
                    const uint32_t bo = (uint32_t)((n0 + half*32 + nb*16 + noff) * LDT + k16 + bkoff) * 2;
                    ldsm_x4(bH[nb][0], bH[nb][1], bH[nb][2], bH[nb][3], sBh + bo);
                    ldsm_x4(bL[nb][0], bL[nb][1], bL[nb][2], bL[nb][3], sBl + bo);
                }
                #pragma unroll
                for (int mi = 0; mi < 4; mi++)
                    #pragma unroll
                    for (int ni2 = 0; ni2 < 4; ni2++) {
                        const int ni = half * 4 + ni2;
                        const uint32_t* bh = &bH[ni2 >> 1][(ni2 & 1) * 2];
                        const uint32_t* bl = &bL[ni2 >> 1][(ni2 & 1) * 2];
                        mma_bf16(acc[mi][ni], aH[mi], bh);
                        mma_bf16(acc[mi][ni], aH[mi], bl);
                        mma_bf16(acc[mi][ni], aL[mi], bh);
                    }
            }
        }
    }
    __syncthreads();   // smem reuse (MODE 1) / uniform exit

    // ------------------------------ epilogue ------------------------------
    if (MODE == 1) {
        float* T = (float*)smem;       // [128][132] fp32 = 67584 B
        #pragma unroll
        for (int mi = 0; mi < 4; mi++)
            #pragma unroll
            for (int ni = 0; ni < 8; ni++) {
                const int ml = m0 + mi*16 + (lane >> 2);
                const int nl = n0 + ni*8 + (lane & 3) * 2;
                const float b0 = bias[bn + nl], b1 = bias[bn + nl + 1];
                T[ml * 132 + nl]           = acc[mi][ni][0] + b0;
                T[ml * 132 + nl + 1]       = acc[mi][ni][1] + b1;
                T[(ml + 8) * 132 + nl]     = acc[mi][ni][2] + b0;
                T[(ml + 8) * 132 + nl + 1] = acc[mi][ni][3] + b1;
            }
        __syncthreads();
        // 4 threads per column, each 32 consecutive m (coalesced 64B/thread)
        const int ncol = tid >> 2;            // 0..31 (loop +32)
        const int ms   = (tid & 3) * 32;
        for (int nn = ncol; nn < 128; nn += 32) {
            uint32_t* ph = (uint32_t*)(Chi + (size_t)(bn + nn) * ldct + bm + ms);
            uint32_t* pl = (uint32_t*)(Clo + (size_t)(bn + nn) * ldct + bm + ms);
            #pragma unroll
            for (int m = 0; m < 32; m += 2) {
                uint32_t hp, lp;
                split_pack(T[(ms + m) * 132 + nn], T[(ms + m + 1) * 132 + nn], hp, lp);
                ph[m >> 1] = hp;  pl[m >> 1] = lp;
            }
        }
    } else {
        #pragma unroll
        for (int mi = 0; mi < 4; mi++)
            #pragma unroll
            for (int ni = 0; ni < 8; ni++) {
                const int rb = bm + m0 + mi*16 + (lane >> 2);
                const int cb = bn + n0 + ni*8 + (lane & 3) * 2;
                #pragma unroll
                for (int half = 0; half < 2; half++) {
                    const int r = rb + half * 8;
                    const float v0 = acc[mi][ni][half*2];
                    const float v1 = acc[mi][ni][half*2 + 1];
                    if (MODE == 0) {
                        __nv_bfloat16* Ch = Chi + (size_t)bz * sC;
                        __nv_bfloat16* Cl = Clo + (size_t)bz * sC;
                        float w0 = v0, w1 = v1;
                        if (bias) { w0 += bias[cb]; w1 += bias[cb + 1]; }
                        uint32_t hp, lp;
                        split_pack(w0, w1, hp, lp);
                        *(uint32_t*)(Ch + (size_t)r * ldc + cb) = hp;
                        *(uint32_t*)(Cl + (size_t)r * ldc + cb) = lp;
                    } else if (MODE == 2) {
                        float* C = Cf + (size_t)bz * sC;
                        const int* mk = maskp + (size_t)bz * sC;
                        const size_t off = (size_t)r * ldc + cb;
                        const float2 pb = *(const float2*)(posb + off);
                        const int2   mm = *(const int2*)(mk + off);
                        float2 o;
                        o.x = mm.x ? fmaf(v0, scale, pb.x) : -1e9f;
                        o.y = mm.y ? fmaf(v1, scale, pb.y) : -1e9f;
                        *(float2*)(C + off) = o;
                    } else {  // MODE 3
                        float2 o;
                        o.x = v0 + bias[cb];
                        o.y = v1 + bias[cb + 1];
                        *(float2*)(Cf + (size_t)r * ldc + cb) = o;
                    }
                }
            }
    }
}

// ---------------------------------------------------------------------------
// xp = x + PE, bf16-split
// ---------------------------------------------------------------------------
__global__ void __launch_bounds__(256) pe_split_kernel(
    const float* __restrict__ x, __nv_bfloat16* __restrict__ xh, __nv_bfloat16* __restrict__ xl)
{
    int i   = blockIdx.x * blockDim.x + threadIdx.x;
    int h2  = i & (HID / 2 - 1);
    int row = i >> 9;
    int s   = row & (SEQ - 1);
    float div = expf((float)(2 * h2) * (-9.210340371976184f / (float)HID));
    float sv, cv;
    sincosf((float)s * div, &sv, &cv);
    int base = 2 * i;
    uint32_t hp, lp;
    split_pack(x[base] + sv, x[base + 1] + cv, hp, lp);
    ((uint32_t*)xh)[i] = hp;
    ((uint32_t*)xl)[i] = lp;
}

// all 4 weight splits in one launch (blockIdx.y selects matrix)
__global__ void __launch_bounds__(256) wsplit4_kernel(
    const float* __restrict__ w0, const float* __restrict__ w1,
    const float* __restrict__ w2, const float* __restrict__ w3,
    __nv_bfloat16* __restrict__ h0, __nv_bfloat16* __restrict__ h1,
    __nv_bfloat16* __restrict__ h2, __nv_bfloat16* __restrict__ h3,
    __nv_bfloat16* __restrict__ l0, __nv_bfloat16* __restrict__ l1,
    __nv_bfloat16* __restrict__ l2, __nv_bfloat16* __restrict__ l3)
{
    const float* w; __nv_bfloat16 *wh, *wl;
    switch (blockIdx.y) {
        case 0:  w = w0; wh = h0; wl = l0; break;
        case 1:  w = w1; wh = h1; wl = l1; break;
        case 2:  w = w2; wh = h2; wl = l2; break;
        default: w = w3; wh = h3; wl = l3; break;
    }
    int i4 = (blockIdx.x * blockDim.x + threadIdx.x) * 4;
    float4 v = *(const float4*)(w + i4);
    uint32_t a0, b0, a1, b1;
    split_pack(v.x, v.y, a0, b0);
    split_pack(v.z, v.w, a1, b1);
    ((uint2*)wh)[i4 >> 2] = make_uint2(a0, a1);
    ((uint2*)wl)[i4 >> 2] = make_uint2(b0, b1);
}

// ---------------------------------------------------------------------------
// softmax; writes fp32 probs to out2 and bf16 split for the attn@V GEMM
// ---------------------------------------------------------------------------
__global__ void __launch_bounds__(256) softmax_split_kernel(
    const float* __restrict__ scores, float* __restrict__ out2,
    __nv_bfloat16* __restrict__ ah, __nv_bfloat16* __restrict__ al)
{
    const size_t row = blockIdx.x;
    const float* p = scores + row * SEQ;
    const int t = threadIdx.x, w = t >> 5, lane = t & 31;

    float4 u0 = *(const float4*)(p + t * 8);
    float4 u1 = *(const float4*)(p + t * 8 + 4);
    float v[8] = {u0.x, u0.y, u0.z, u0.w, u1.x, u1.y, u1.z, u1.w};

    float m = v[0];
    #pragma unroll
    for (int i = 1; i < 8; i++) m = fmaxf(m, v[i]);
    #pragma unroll
    for (int o = 16; o; o >>= 1) m = fmaxf(m, __shfl_xor_sync(0xffffffffu, m, o));
    __shared__ float smax[8], ssum[8];
    if (lane == 0) smax[w] = m;
    __syncthreads();
    float rm = smax[0];
    #pragma unroll
    for (int i = 1; i < 8; i++) rm = fmaxf(rm, smax[i]);

    float s = 0.f;
    #pragma unroll
    for (int i = 0; i < 8; i++) { v[i] = expf(v[i] - rm); s += v[i]; }
    #pragma unroll
    for (int o = 16; o; o >>= 1) s += __shfl_xor_sync(0xffffffffu, s, o);
    if (lane == 0) ssum[w] = s;
    __syncthreads();
    float tot = 0.f;
    #pragma unroll
    for (int i = 0; i < 8; i++) tot += ssum[i];
    const float inv = 1.f / tot;
    #pragma unroll
    for (int i = 0; i < 8; i++) v[i] *= inv;

    float* po = out2 + row * SEQ + t * 8;
    *(float4*)(po)     = make_float4(v[0], v[1], v[2], v[3]);
    *(float4*)(po + 4) = make_float4(v[4], v[5], v[6], v[7]);

    uint32_t* ph = (uint32_t*)(ah + row * SEQ) + t * 4;
    uint32_t* pl = (uint32_t*)(al + row * SEQ) + t * 4;
    #pragma unroll
    for (int i = 0; i < 4; i++) {
        uint32_t hp, lp;
        split_pack(v[2 * i], v[2 * i + 1], hp, lp);
        ph[i] = hp;  pl[i] = lp;
    }
}

// ---------------------------------------------------------------------------
// LayerNorm(o + x)
// ---------------------------------------------------------------------------
__global__ void __launch_bounds__(256) ln_kernel(
    const float* __restrict__ o, const float* __restrict__ x,
    const float* __restrict__ gamma, const float* __restrict__ beta,
    float* __restrict__ out)
{
    const size_t row = blockIdx.x;
    const float* po = o + row * HID;
    const float* px = x + row * HID;
    float* pout = out + row * HID;
    const int t = threadIdx.x, w = t >> 5, lane = t & 31;

    float4 a = *(const float4*)(po + t * 4);
    float4 b = *(const float4*)(px + t * 4);
    float h[4] = {a.x + b.x, a.y + b.y, a.z + b.z, a.w + b.w};

    float s  = h[0] + h[1] + h[2] + h[3];
    float sq = h[0]*h[0] + h[1]*h[1] + h[2]*h[2] + h[3]*h[3];
    #pragma unroll
    for (int off = 16; off; off >>= 1) {
        s  += __shfl_xor_sync(0xffffffffu, s,  off);
        sq += __shfl_xor_sync(0xffffffffu, sq, off);
    }
    __shared__ float rs[8], rq[8];
    if (lane == 0) { rs[w] = s; rq[w] = sq; }
    __syncthreads();
    float ts = 0.f, tq = 0.f;
    #pragma unroll
    for (int i = 0; i < 8; i++) { ts += rs[i]; tq += rq[i]; }

    const float mu  = ts * (1.f / HID);
    const float var = tq * (1.f / HID) - mu * mu;
    const float r   = rsqrtf(var + 1e-5f);

    float4 gv = *(const float4*)(gamma + t * 4);
    float4 bv = *(const float4*)(beta  + t * 4);
    float4 ov;
    ov.x = (h[0] - mu) * r * gv.x + bv.x;
    ov.y = (h[1] - mu) * r * gv.y + bv.y;
    ov.z = (h[2] - mu) * r * gv.z + bv.z;
    ov.w = (h[3] - mu) * r * gv.w + bv.w;
    *(float4*)(pout + t * 4) = ov;
}

// ---------------------------------------------------------------------------
// Launch
// ---------------------------------------------------------------------------
extern "C" void kernel_launch(void* const* d_in, const int* in_sizes, int n_in,
                              void* d_out, int out_size)
{
    const float* x     = (const float*)d_in[0];
    const int*   mask  = (const int*)  d_in[1];
    const float* Wq    = (const float*)d_in[2];
    const float* bq    = (const float*)d_in[3];
    const float* Wk    = (const float*)d_in[4];
    const float* bk    = (const float*)d_in[5];
    const float* Wv    = (const float*)d_in[6];
    const float* bv    = (const float*)d_in[7];
    const float* posb  = (const float*)d_in[8];
    const float* Wo    = (const float*)d_in[9];
    const float* bo    = (const float*)d_in[10];
    const float* gamma = (const float*)d_in[11];
    const float* beta  = (const float*)d_in[12];
    float* out  = (float*)d_out;
    float* out2 = out + (size_t)MT * HID;

    __nv_bfloat16 *xph, *xpl, *qh, *ql, *kh, *kl, *vth, *vtl, *cxh, *cxl;
    __nv_bfloat16 *wqh, *wql, *wkh, *wkl, *wvh, *wvl, *woh, *wol, *ath, *atl;
    float *scores, *o;
    cudaGetSymbolAddress((void**)&xph, g_xp_h);  cudaGetSymbolAddress((void**)&xpl, g_xp_l);
    cudaGetSymbolAddress((void**)&qh,  g_q_h);   cudaGetSymbolAddress((void**)&ql,  g_q_l);
    cudaGetSymbolAddress((void**)&kh,  g_k_h);   cudaGetSymbolAddress((void**)&kl,  g_k_l);
    cudaGetSymbolAddress((void**)&vth, g_vt_h);  cudaGetSymbolAddress((void**)&vtl, g_vt_l);
    cudaGetSymbolAddress((void**)&cxh, g_cx_h);  cudaGetSymbolAddress((void**)&cxl, g_cx_l);
    cudaGetSymbolAddress((void**)&wqh, g_wq_h);  cudaGetSymbolAddress((void**)&wql, g_wq_l);
    cudaGetSymbolAddress((void**)&wkh, g_wk_h);  cudaGetSymbolAddress((void**)&wkl, g_wk_l);
    cudaGetSymbolAddress((void**)&wvh, g_wv_h);  cudaGetSymbolAddress((void**)&wvl, g_wv_l);
    cudaGetSymbolAddress((void**)&woh, g_wo_h);  cudaGetSymbolAddress((void**)&wol, g_wo_l);
    cudaGetSymbolAddress((void**)&ath, g_at_h);  cudaGetSymbolAddress((void**)&atl, g_at_l);
    cudaGetSymbolAddress((void**)&scores, g_scores);
    cudaGetSymbolAddress((void**)&o, g_o);

    cudaFuncSetAttribute(tc_gemm<0>, cudaFuncAttributeMaxDynamicSharedMemorySize, SMEM_BYTES);
    cudaFuncSetAttribute(tc_gemm<1>, cudaFuncAttributeMaxDynamicSharedMemorySize, SMEM_BYTES);
    cudaFuncSetAttribute(tc_gemm<2>, cudaFuncAttributeMaxDynamicSharedMemorySize, SMEM_BYTES);
    cudaFuncSetAttribute(tc_gemm<3>, cudaFuncAttributeMaxDynamicSharedMemorySize, SMEM_BYTES);

    // 0) xp = x + PE, split
    pe_split_kernel<<<(MT * HID / 2) / 256, 256>>>(x, xph, xpl);

    // 1) weight splits (single launch)
    dim3 wgrid((HID * HID / 4) / 256, 4, 1);
    wsplit4_kernel<<<wgrid, 256>>>(Wq, Wk, Wv, Wo, wqh, wkh, wvh, woh, wql, wkl, wvl, wol);

    // 2-4) Q/K/V projections  [8192,1024] @ W^T + b
    dim3 gp(HID / 128, MT / 128, 1);
    tc_gemm<0><<<gp, 128, SMEM_BYTES>>>(xph, xpl, wqh, wql, HID, HID, HID, 0, 0, 0,
        nullptr, qh, ql, HID, 0, bq, nullptr, nullptr, 0.f);
    tc_gemm<0><<<gp, 128, SMEM_BYTES>>>(xph, xpl, wkh, wkl, HID, HID, HID, 0, 0, 0,
        nullptr, kh, kl, HID, 0, bk, nullptr, nullptr, 0.f);
    tc_gemm<1><<<gp, 128, SMEM_BYTES>>>(xph, xpl, wvh, wvl, HID, HID, HID, 0, 0, 0,
        nullptr, vth, vtl, 0, MT, bv, nullptr, nullptr, 0.f);

    // 5) scores = QK^T/32 + pos_bias, masked   <-- launch index 5 (profiled)
    dim3 gs(SEQ / 128, SEQ / 128, NB);
    tc_gemm<2><<<gs, 128, SMEM_BYTES>>>(qh, ql, kh, kl, HID, HID, HID,
        (long long)SEQ * HID, (long long)SEQ * HID, (long long)SEQ * SEQ,
        scores, nullptr, nullptr, SEQ, 0, nullptr, posb, mask, 0.03125f);

    // 6) softmax + split (+ attn probs output)
    softmax_split_kernel<<<MT, 256>>>(scores, out2, ath, atl);

    // 7) context = attn @ V   (B = V^T, NT)
    dim3 gc(HID / 128, SEQ / 128, NB);
    tc_gemm<0><<<gc, 128, SMEM_BYTES>>>(ath, atl, vth, vtl, SEQ, SEQ, MT,
        (long long)SEQ * SEQ, (long long)SEQ, (long long)SEQ * HID,
        nullptr, cxh, cxl, HID, 0, nullptr, nullptr, nullptr, 0.f);

    // 8) output projection -> o (fp32)
    tc_gemm<3><<<gp, 128, SMEM_BYTES>>>(cxh, cxl, woh, wol, HID, HID, HID, 0, 0, 0,
        o, nullptr, nullptr, HID, 0, bo, nullptr, nullptr, 0.f);

    // 9) LayerNorm(o + x)
    ln_kernel<<<MT, 256>>>(o, x, gamma, beta, out);
}